// round 8
// baseline (speedup 1.0000x reference)
#include <cuda_runtime.h>
#include <math.h>

// ---------------------------------------------------------------------------
// ChebConv2D  (B=32, C=64, H=W=128, O=64, K=9)  -- 3-launch pipeline
//
//  L1: M[b,c,a,bb] = T^T x T   (2048 blks, setup-independent, recurrence+parity)
//      || Gi = (T^T T)^-1      (1 blk)
//      || Wc[j,f,c] = sum_o W_w[c,o,kw] W_h[o,f,kh]   (81 blks)
//  L2: ch = Gi M Gi^T ; e[b,f,j] = sum_c ch Wc        (128 blks)
//  L3: out = Te e Te^T          (2048 blks, recurrence+parity)
// ---------------------------------------------------------------------------

#define BB   32
#define CC   64
#define HH   128
#define WW   128
#define OO   64
#define KK   9
#define KK2  81
#define BC   (BB*CC)     // 2048
#define BF   (BB*OO)     // 2048
#define IMG  (HH*WW)     // 16384

__device__ float g_Gi[KK2];          // Ginv[kh][a]
__device__ float g_M [KK2*BC];       // [a*9+b][bc]   raw moments
__device__ float g_wc[(size_t)KK2*OO*CC]; // [j][f][c]
__device__ float g_e [BF*KK2];       // [bf][j]

__device__ __forceinline__ float xn_of(int i) {
    double xd = (double)i / 127.0;
    float  xf = (float)xd;
    float  v  = 2.0f * xf - 1.0f;
    return fminf(fmaxf(v, -1.0f + 1e-6f), 1.0f - 1e-6f);
}

// ---------------------------------------------------------------------------
// L1: heterogeneous launch. blocks [0,2048): moments; 2048: Gi; 2049+: Wc.
// Shared buffer unioned across branches to keep k1 occupancy.
// ---------------------------------------------------------------------------
__global__ __launch_bounds__(256) void kL1(const float* __restrict__ x,
                                           const float* __restrict__ Ww,
                                           const float* __restrict__ Wh) {
    __shared__ __align__(16) char sbuf[43200];
    int tid = threadIdx.x;
    int bid = blockIdx.x;

    if (bid < BC) {
        // ----------------- moments M = T^T x T for one (b,c) ---------------
        float* red = (float*)sbuf;                    // [8][9][132]  38016 B
        float* tew = (float*)(sbuf + 38016);          // [128][9]      4608 B
        float* xs  = (float*)(sbuf + 38016 + 4608);   // [128]          512 B

        if (tid < HH) {
            float xn = xn_of(tid);
            xs[tid] = xn;
            float x2 = xn + xn, t0 = 1.0f, t1 = xn;
            tew[tid*KK + 0] = 1.0f;
            tew[tid*KK + 1] = xn;
            #pragma unroll
            for (int k = 2; k < KK; k++) {
                float t2 = x2*t1 - t0;
                tew[tid*KK + k] = t2;
                t0 = t1; t1 = t2;
            }
        }
        __syncthreads();

        int s  = tid >> 5;              // 0..7 -> h pairs [s*8, s*8+8)
        int w4 = (tid & 31) * 4;
        const float* xg = x + (size_t)bid * IMG + w4;

        float acc[KK][4];
        #pragma unroll
        for (int k = 0; k < KK; k++)
            #pragma unroll
            for (int i = 0; i < 4; i++) acc[k][i] = 0.0f;

        #pragma unroll 4
        for (int pp = 0; pp < 8; pp++) {
            int h = s*8 + pp;           // lo row; hi = 127-h
            float4 lo = *(const float4*)(xg + h*WW);
            float4 hi = *(const float4*)(xg + (127-h)*WW);
            float sx = lo.x + hi.x, sy = lo.y + hi.y, sz = lo.z + hi.z, sw = lo.w + hi.w;
            float dx = lo.x - hi.x, dy = lo.y - hi.y, dz = lo.z - hi.z, dw = lo.w - hi.w;
            float xn = xs[h], x2 = xn + xn;
            acc[0][0] += sx; acc[0][1] += sy; acc[0][2] += sz; acc[0][3] += sw;
            float t0 = 1.0f, t1 = xn;
            acc[1][0] += t1*dx; acc[1][1] += t1*dy; acc[1][2] += t1*dz; acc[1][3] += t1*dw;
            #pragma unroll
            for (int k = 2; k < KK; k++) {
                float t2 = x2*t1 - t0;
                if ((k & 1) == 0) {
                    acc[k][0] += t2*sx; acc[k][1] += t2*sy;
                    acc[k][2] += t2*sz; acc[k][3] += t2*sw;
                } else {
                    acc[k][0] += t2*dx; acc[k][1] += t2*dy;
                    acc[k][2] += t2*dz; acc[k][3] += t2*dw;
                }
                t0 = t1; t1 = t2;
            }
        }

        #pragma unroll
        for (int k = 0; k < KK; k++)
            *(float4*)(red + (s*KK + k)*132 + w4) =
                make_float4(acc[k][0], acc[k][1], acc[k][2], acc[k][3]);
        __syncthreads();

        // reduce 8 slices into slice 0
        for (int i = tid; i < KK*HH; i += 256) {
            int k = i >> 7, w = i & 127;
            float v = 0.0f;
            #pragma unroll
            for (int ss = 0; ss < 8; ss++) v += red[(ss*KK + k)*132 + w];
            red[k*132 + w] = v;
        }
        __syncthreads();

        // width analysis with w-parity: M[a][b] = sum_{w<64} (red[w] +- red[127-w]) T[w][b]
        if (tid < KK2) {
            int a = tid / KK, b = tid % KK;
            float sgn = (b & 1) ? -1.0f : 1.0f;
            float sum = 0.0f;
            #pragma unroll 4
            for (int w = 0; w < 64; w++) {
                float v = red[a*132 + w] + sgn * red[a*132 + 127 - w];
                sum += v * tew[w*KK + b];
            }
            g_M[(size_t)tid * BC + bid] = sum;
        }
    } else if (bid == BC) {
        // ----------------- Gi = (T^T T)^-1 ---------------------------------
        float* Tf = (float*)sbuf;                  // [128][9]
        float* Gm = (float*)(sbuf + 4608);         // [9][19]

        if (tid < HH) {
            float xn = xn_of(tid);
            float x2 = xn + xn, t0 = 1.0f, t1 = xn;
            Tf[tid*KK + 0] = 1.0f;
            Tf[tid*KK + 1] = xn;
            #pragma unroll
            for (int k = 2; k < KK; k++) {
                float t2 = x2*t1 - t0;
                Tf[tid*KK + k] = t2;
                t0 = t1; t1 = t2;
            }
        }
        __syncthreads();

        if (tid < KK2) {
            int a = tid / KK, b = tid % KK;
            float s0 = 0.f, s1 = 0.f, s2 = 0.f, s3 = 0.f;
            #pragma unroll 4
            for (int j = 0; j < HH; j += 4) {
                s0 += Tf[(j+0)*KK + a] * Tf[(j+0)*KK + b];
                s1 += Tf[(j+1)*KK + a] * Tf[(j+1)*KK + b];
                s2 += Tf[(j+2)*KK + a] * Tf[(j+2)*KK + b];
                s3 += Tf[(j+3)*KK + a] * Tf[(j+3)*KK + b];
            }
            Gm[a*19 + b]     = (s0+s1) + (s2+s3);
            Gm[a*19 + 9 + b] = (a == b) ? 1.0f : 0.0f;
        }
        __syncthreads();

        if (tid < 32) {                 // warp-level Gauss-Jordan (SPD)
            int lane = tid;
            for (int p = 0; p < KK; p++) {
                float pv = Gm[p*19 + p];
                __syncwarp();
                if (lane < 18) Gm[p*19 + lane] /= pv;
                __syncwarp();
                float fac[KK];
                #pragma unroll
                for (int r = 0; r < KK; r++) fac[r] = Gm[r*19 + p];
                __syncwarp();
                if (lane < 18) {
                    #pragma unroll
                    for (int r = 0; r < KK; r++)
                        if (r != p) Gm[r*19 + lane] -= fac[r] * Gm[p*19 + lane];
                }
                __syncwarp();
            }
        }
        __syncthreads();

        if (tid < KK2)
            g_Gi[tid] = Gm[(tid / KK)*19 + 9 + tid % KK];
    } else {
        // ----------------- Wc[j][f][c] = sum_o Ww[c,o,kw]*Wh[o,f,kh] -------
        float* sww = (float*)sbuf;                 // [64][65]  16640 B
        float* swh = (float*)(sbuf + 16640);       // [64][64]  16384 B
        int j  = bid - BC - 1;
        int kh = j / KK, kw = j % KK;

        for (int i = tid; i < CC*OO; i += 256) {
            int c = i >> 6, o = i & 63;
            sww[c*65 + o] = Ww[(c*OO + o)*KK + kw];
            swh[i]        = Wh[i*KK + kh];        // i = o*64+f
        }
        __syncthreads();

        int c  = tid & 63;
        int f0 = (tid >> 6) * 16;
        float acc[16];
        #pragma unroll
        for (int i = 0; i < 16; i++) acc[i] = 0.0f;
        for (int o = 0; o < OO; o++) {
            float wv = sww[c*65 + o];
            #pragma unroll
            for (int i = 0; i < 16; i++)
                acc[i] += wv * swh[o*OO + f0 + i];
        }
        float* wcj = g_wc + (size_t)j * OO * CC;
        #pragma unroll
        for (int i = 0; i < 16; i++)
            wcj[(f0 + i)*CC + c] = acc[i];        // lanes (c) contiguous
    }
}

// ---------------------------------------------------------------------------
// L2: per (b, f-group of 16): ch = Gi M Gi^T, then e = sum_c ch * Wc
// grid = 32*4 = 128 blocks, 256 threads.
// ---------------------------------------------------------------------------
__global__ __launch_bounds__(256) void kL2() {
    __shared__ float Ms [CC*84];       // [c][j]  (M, then ch in-place)
    __shared__ float tmp[CC*84];
    __shared__ float gis[KK2];
    int tid = threadIdx.x;
    int b   = blockIdx.x >> 2;
    int f0  = (blockIdx.x & 3) * 16;

    for (int i = tid; i < CC*KK2; i += 256) {
        int c = i & 63, j = i >> 6;
        Ms[c*84 + j] = g_M[(size_t)j * BC + b*CC + c];   // coalesced over c
    }
    if (tid < KK2) gis[tid] = g_Gi[tid];
    __syncthreads();

    // pass1: tmp[c][kh*9+bb] = sum_a Gi[kh,a] * M[c][a*9+bb]
    for (int i = tid; i < CC*KK2; i += 256) {
        int c = i / KK2, r = i % KK2;
        int kh = r / KK, bb = r % KK;
        float s = 0.0f;
        #pragma unroll
        for (int a = 0; a < KK; a++)
            s += gis[kh*KK + a] * Ms[c*84 + a*KK + bb];
        tmp[c*84 + r] = s;
    }
    __syncthreads();

    // pass2: ch[c][kh*9+kw] = sum_bb tmp[c][kh*9+bb] * Gi[kw,bb]  (into Ms)
    for (int i = tid; i < CC*KK2; i += 256) {
        int c = i / KK2, r = i % KK2;
        int kh = r / KK, kw = r % KK;
        float s = 0.0f;
        #pragma unroll
        for (int bb = 0; bb < KK; bb++)
            s += tmp[c*84 + kh*KK + bb] * gis[kw*KK + bb];
        Ms[c*84 + r] = s;
    }
    __syncthreads();

    // e[b, f0+fi, j] = sum_c ch[c][j] * Wc[j][f0+fi][c]
    int fi = tid >> 4, jt = tid & 15;
    int f  = f0 + fi;
    for (int j = jt; j < KK2; j += 16) {
        const float4* wrow = (const float4*)(g_wc + ((size_t)j * OO + f) * CC);
        float s0 = 0.f, s1 = 0.f, s2 = 0.f, s3 = 0.f;
        #pragma unroll 4
        for (int cq = 0; cq < 16; cq++) {
            float4 wv = wrow[cq];
            s0 += Ms[(cq*4+0)*84 + j] * wv.x;
            s1 += Ms[(cq*4+1)*84 + j] * wv.y;
            s2 += Ms[(cq*4+2)*84 + j] * wv.z;
            s3 += Ms[(cq*4+3)*84 + j] * wv.w;
        }
        g_e[(size_t)(b*OO + f) * KK2 + j] = (s0+s1) + (s2+s3);
    }
}

// ---------------------------------------------------------------------------
// L3: out = Te e Te^T with parity on h; tables built in-block.
// one block per (b,f); 256 threads = (4 w's, 8 h-pairs); float4 stores.
// ---------------------------------------------------------------------------
__global__ __launch_bounds__(256) void kL3(float* __restrict__ out) {
    __shared__ __align__(16) float vs[KK*132];     // [kh][w] padded
    __shared__ float es[KK2];
    __shared__ float xs[HH];
    int tid = threadIdx.x;
    int bf  = blockIdx.x;

    if (tid < HH) xs[tid] = xn_of(tid);
    else if (tid < HH + KK2) es[tid-HH] = g_e[(size_t)bf * KK2 + (tid-HH)];
    __syncthreads();

    // v[kh][w] via width recurrence; all 256 threads (kh split 0..3 / 4..8)
    {
        int w  = tid & 127;
        int hi = tid >> 7;
        float xn = xs[w], x2 = xn + xn;
        float tw[KK];
        tw[0] = 1.0f; tw[1] = xn;
        #pragma unroll
        for (int k = 2; k < KK; k++) tw[k] = x2*tw[k-1] - tw[k-2];
        int kh0 = hi ? 4 : 0;
        int kh1 = hi ? 9 : 4;
        for (int kh = kh0; kh < kh1; kh++) {
            float sv = 0.0f;
            #pragma unroll
            for (int kw = 0; kw < KK; kw++) sv += es[kh*KK + kw] * tw[kw];
            vs[kh*132 + w] = sv;
        }
    }
    __syncthreads();

    int w4 = (tid & 31) * 4;
    int s  = tid >> 5;                  // 0..7 -> h pairs [s*8, s*8+8)
    float4 vr[KK];
    #pragma unroll
    for (int k = 0; k < KK; k++) vr[k] = *(const float4*)(vs + k*132 + w4);

    float* op = out + (size_t)bf * IMG + w4;
    #pragma unroll 4
    for (int pp = 0; pp < 8; pp++) {
        int h = s*8 + pp;               // lo row; hi = 127-h
        float xn = xs[h], x2 = xn + xn;
        float4 E, O;
        E.x = vr[0].x; E.y = vr[0].y; E.z = vr[0].z; E.w = vr[0].w;
        float t0 = 1.0f, t1 = xn;
        O.x = t1*vr[1].x; O.y = t1*vr[1].y; O.z = t1*vr[1].z; O.w = t1*vr[1].w;
        #pragma unroll
        for (int k = 2; k < KK; k++) {
            float t2 = x2*t1 - t0;
            if ((k & 1) == 0) {
                E.x += t2*vr[k].x; E.y += t2*vr[k].y;
                E.z += t2*vr[k].z; E.w += t2*vr[k].w;
            } else {
                O.x += t2*vr[k].x; O.y += t2*vr[k].y;
                O.z += t2*vr[k].z; O.w += t2*vr[k].w;
            }
            t0 = t1; t1 = t2;
        }
        float4 lo, hi;
        lo.x = E.x + O.x; lo.y = E.y + O.y; lo.z = E.z + O.z; lo.w = E.w + O.w;
        hi.x = E.x - O.x; hi.y = E.y - O.y; hi.z = E.z - O.z; hi.w = E.w - O.w;
        *(float4*)(op + h*WW)       = lo;
        *(float4*)(op + (127-h)*WW) = hi;
    }
}

// ---------------------------------------------------------------------------
extern "C" void kernel_launch(void* const* d_in, const int* in_sizes, int n_in,
                              void* d_out, int out_size) {
    const float* x  = (const float*)d_in[0];
    const float* Ww = (const float*)d_in[1];
    const float* Wh = (const float*)d_in[2];
    float* out = (float*)d_out;

    kL1<<<BC + 1 + KK2, 256>>>(x, Ww, Wh);
    kL2<<<BB*4, 256>>>();
    kL3<<<BF, 256>>>(out);
}

// round 9
// speedup vs baseline: 1.3181x; 1.3181x over previous
#include <cuda_runtime.h>
#include <math.h>

// ---------------------------------------------------------------------------
// ChebConv2D  (B=32, C=64, H=W=128, O=64, K=9)
//
//   M [b,c,a,bb]  = sum_h sum_w T[h,a] x[b,c,h,w] T[w,bb]   (k1, recurrence+parity)
//   ch[b,c,kh,kw] = Ginv M Ginv^T                           (k1 tail)
//   Wc[kh,kw,c,f] = sum_o W_w[c,o,kw] * W_h[o,f,kh]         (setup)
//   e [b,f,kh,kw] = sum_c ch[b,c,kh,kw] * Wc[kh,kw,c,f]     (k_mix)
//   out[b,f,h,w]  = Te * e * Te^T                           (k4, recurrence+parity)
//
// R9: k1 main loop batches 4 h-pairs of LDG.128 (8 independent loads) before
// computing, to raise memory-level parallelism (k1 was latency-bound at 33%occ).
// ---------------------------------------------------------------------------

#define BB   32
#define CC   64
#define HH   128
#define WW   128
#define OO   64
#define KK   9
#define KK2  81
#define BC   (BB*CC)     // 2048
#define BF   (BB*OO)     // 2048
#define IMG  (HH*WW)     // 16384

__device__ float g_Te[HH*KK];        // T[i][k], i*9+k
__device__ float g_Gi[KK2];          // Ginv[kh][a]
__device__ float g_xn[HH];           // clamped chebyshev abscissae
__device__ float g_ch[KK2*BC];       // [j][b*64+c]
__device__ float g_wc[KK2*CC*OO];    // [j][c][f]
__device__ float g_e [BF*KK2];       // [b*64+f][j]

// ---------------------------------------------------------------------------
// kA: block 0 = Chebyshev setup (fp32, warp-level GJ);
//     blocks 1..81 = combined weight Wc[j][c][f]
// ---------------------------------------------------------------------------
__global__ __launch_bounds__(256) void kA_setup_wc(const float* __restrict__ Ww,
                                                   const float* __restrict__ Wh) {
    int tid = threadIdx.x;

    if (blockIdx.x == 0) {
        __shared__ float Tf[HH*KK];       // T[i][k]
        __shared__ float Gm[KK][19];      // augmented [G | I]

        if (tid < HH) {
            double xd = (double)tid / 127.0;
            float  xf = (float)xd;
            float  xn = 2.0f * xf - 1.0f;
            xn = fminf(fmaxf(xn, -1.0f + 1e-6f), 1.0f - 1e-6f);
            g_xn[tid] = xn;
            float x2 = xn + xn;
            float t0 = 1.0f, t1 = xn;
            Tf[tid*KK + 0] = 1.0f;  g_Te[tid*KK + 0] = 1.0f;
            Tf[tid*KK + 1] = t1;    g_Te[tid*KK + 1] = t1;
            #pragma unroll
            for (int k = 2; k < KK; k++) {
                float t2 = x2*t1 - t0;
                Tf[tid*KK + k] = t2;
                g_Te[tid*KK + k] = t2;
                t0 = t1; t1 = t2;
            }
        }
        __syncthreads();

        if (tid < KK2) {
            int a = tid / KK, b = tid % KK;
            float s0 = 0.f, s1 = 0.f, s2 = 0.f, s3 = 0.f;
            #pragma unroll 4
            for (int j = 0; j < HH; j += 4) {
                s0 += Tf[(j+0)*KK + a] * Tf[(j+0)*KK + b];
                s1 += Tf[(j+1)*KK + a] * Tf[(j+1)*KK + b];
                s2 += Tf[(j+2)*KK + a] * Tf[(j+2)*KK + b];
                s3 += Tf[(j+3)*KK + a] * Tf[(j+3)*KK + b];
            }
            Gm[a][b]     = (s0+s1) + (s2+s3);
            Gm[a][9 + b] = (a == b) ? 1.0f : 0.0f;
        }
        __syncthreads();

        if (tid < 32) {                   // warp-level Gauss-Jordan
            int lane = tid;
            for (int p = 0; p < KK; p++) {
                float pv = Gm[p][p];
                __syncwarp();
                if (lane < 18) Gm[p][lane] /= pv;
                __syncwarp();
                float fac[KK];
                #pragma unroll
                for (int r = 0; r < KK; r++) fac[r] = Gm[r][p];
                __syncwarp();
                if (lane < 18) {
                    #pragma unroll
                    for (int r = 0; r < KK; r++)
                        if (r != p) Gm[r][lane] -= fac[r] * Gm[p][lane];
                }
                __syncwarp();
            }
        }
        __syncthreads();

        if (tid < KK2)
            g_Gi[tid] = Gm[tid / KK][9 + tid % KK];
    } else {
        // Wc[j][c][f] = sum_o Ww[c,o,kw]*Wh[o,f,kh]
        __shared__ float sww[CC*(OO+1)];
        __shared__ float swh[OO*OO];
        int j  = blockIdx.x - 1;
        int kh = j / KK, kw = j % KK;

        for (int i = tid; i < CC*OO; i += 256) {
            int c = i >> 6, o = i & 63;
            sww[c*(OO+1) + o] = Ww[(c*OO + o)*KK + kw];
            swh[i]            = Wh[i*KK + kh];
        }
        __syncthreads();

        int f  = tid & 63;
        int c0 = (tid >> 6) * 16;
        float acc[16];
        #pragma unroll
        for (int i = 0; i < 16; i++) acc[i] = 0.0f;
        for (int o = 0; o < OO; o++) {
            float wh = swh[o*OO + f];
            #pragma unroll
            for (int i = 0; i < 16; i++)
                acc[i] += sww[(c0 + i)*(OO+1) + o] * wh;
        }
        float* wcj = g_wc + (size_t)j * CC * OO;
        #pragma unroll
        for (int i = 0; i < 16; i++)
            wcj[(c0 + i)*OO + f] = acc[i];
    }
}

// ---------------------------------------------------------------------------
// K1: per (b,c) image -> ch[j][bc]. Batched float4 LDG (8 in flight) +
// h-recurrence + parity fold.
// 128 threads: thread = (pair-slice s = tid>>5 of 16 h-pairs, 4 w-cols)
// ---------------------------------------------------------------------------
__global__ __launch_bounds__(128) void k1_analysis(const float* __restrict__ x) {
    __shared__ __align__(16) float red[4*KK*132];  // [s][a][w] padded
    __shared__ float xs[HH];            // xn abscissae
    __shared__ float tew[HH*KK];        // T[w][b] for width-analysis tail
    __shared__ float Ms[KK2];
    __shared__ float tmp[KK2];
    __shared__ float gi[KK2];

    int tid = threadIdx.x;
    int bc  = blockIdx.x;
    int s   = tid >> 5;                 // 0..3 -> h pairs [s*16, s*16+16)
    int w4  = (tid & 31) * 4;

    if (tid < HH) xs[tid] = g_xn[tid];
    for (int i = tid; i < HH*KK; i += 128) tew[i] = g_Te[i];
    if (tid < KK2) gi[tid] = g_Gi[tid];
    __syncthreads();

    const float* xg = x + (size_t)bc * IMG + w4;

    float acc[KK][4];
    #pragma unroll
    for (int k = 0; k < KK; k++)
        #pragma unroll
        for (int i = 0; i < 4; i++) acc[k][i] = 0.0f;

    // 16 h-pairs in batches of 4: issue 8 independent LDG.128, then compute.
    #pragma unroll
    for (int pb = 0; pb < 16; pb += 4) {
        float4 lo[4], hi[4];
        #pragma unroll
        for (int q = 0; q < 4; q++) {
            int h = s*16 + pb + q;
            lo[q] = *(const float4*)(xg + h*WW);
            hi[q] = *(const float4*)(xg + (127-h)*WW);
        }
        #pragma unroll
        for (int q = 0; q < 4; q++) {
            int h = s*16 + pb + q;
            float sx = lo[q].x + hi[q].x, sy = lo[q].y + hi[q].y;
            float sz = lo[q].z + hi[q].z, sw = lo[q].w + hi[q].w;
            float dx = lo[q].x - hi[q].x, dy = lo[q].y - hi[q].y;
            float dz = lo[q].z - hi[q].z, dw = lo[q].w - hi[q].w;
            float xn = xs[h], x2 = xn + xn;
            acc[0][0] += sx; acc[0][1] += sy; acc[0][2] += sz; acc[0][3] += sw;
            float t0 = 1.0f, t1 = xn;
            acc[1][0] += t1*dx; acc[1][1] += t1*dy; acc[1][2] += t1*dz; acc[1][3] += t1*dw;
            #pragma unroll
            for (int k = 2; k < KK; k++) {
                float t2 = x2*t1 - t0;
                if ((k & 1) == 0) {
                    acc[k][0] += t2*sx; acc[k][1] += t2*sy;
                    acc[k][2] += t2*sz; acc[k][3] += t2*sw;
                } else {
                    acc[k][0] += t2*dx; acc[k][1] += t2*dy;
                    acc[k][2] += t2*dz; acc[k][3] += t2*dw;
                }
                t0 = t1; t1 = t2;
            }
        }
    }

    // partials -> smem: red[s][a][w]
    #pragma unroll
    for (int k = 0; k < KK; k++)
        *(float4*)(red + (s*KK + k)*132 + w4) =
            make_float4(acc[k][0], acc[k][1], acc[k][2], acc[k][3]);
    __syncthreads();

    // reduce slices: red[0][a][w] = sum_s
    {
        int w = tid;
        #pragma unroll
        for (int k = 0; k < KK; k++) {
            float v = red[(0*KK + k)*132 + w] + red[(1*KK + k)*132 + w]
                    + red[(2*KK + k)*132 + w] + red[(3*KK + k)*132 + w];
            red[k*132 + w] = v;
        }
    }
    __syncthreads();

    // width analysis with w-parity: M[a][b] = sum_{w<64} (red[w] +- red[127-w]) T[w][b]
    if (tid < KK2) {
        int a = tid / KK, b = tid % KK;
        float sgn = (b & 1) ? -1.0f : 1.0f;
        float sum = 0.0f;
        #pragma unroll 4
        for (int w = 0; w < 64; w++) {
            float v = red[a*132 + w] + sgn * red[a*132 + 127 - w];
            sum += v * tew[w*KK + b];
        }
        Ms[tid] = sum;
    }
    __syncthreads();

    // ch = Ginv * M * Ginv^T
    if (tid < KK2) {
        int kh = tid / KK, b = tid % KK;
        float sum = 0.0f;
        #pragma unroll
        for (int a = 0; a < KK; a++)
            sum += gi[kh*KK + a] * Ms[a*KK + b];
        tmp[tid] = sum;
    }
    __syncthreads();
    if (tid < KK2) {
        int kh = tid / KK, kw = tid % KK;
        float sum = 0.0f;
        #pragma unroll
        for (int b = 0; b < KK; b++)
            sum += tmp[kh*KK + b] * gi[kw*KK + b];
        g_ch[(size_t)tid * BC + bc] = sum;
    }
}

// ---------------------------------------------------------------------------
// K_mix: e[b,f,j] = sum_c ch[j][b,c] * Wc[j][c][f].
// grid = 81 j * 4 b-groups (8 b each); 256 threads: (f, 4 b-pairs)
// ---------------------------------------------------------------------------
__global__ __launch_bounds__(256) void k_mix() {
    __shared__ float chs[8*CC];        // [bl][c]
    __shared__ float wcs[CC*OO];       // [c][f]
    int tid = threadIdx.x;
    int j   = blockIdx.x >> 2;
    int b0  = (blockIdx.x & 3) * 8;

    for (int i = tid; i < 8*CC; i += 256)
        chs[i] = g_ch[(size_t)j * BC + b0*CC + i];
    for (int i = tid; i < CC*OO; i += 256)
        wcs[i] = g_wc[(size_t)j * CC * OO + i];
    __syncthreads();

    int f  = tid & 63;
    int bl = (tid >> 6) * 2;
    float a0 = 0.0f, a1 = 0.0f;
    #pragma unroll 8
    for (int c = 0; c < CC; c++) {
        float wv = wcs[c*OO + f];
        a0 += chs[bl*CC + c]     * wv;
        a1 += chs[(bl+1)*CC + c] * wv;
    }
    g_e[(size_t)((b0 + bl    )*OO + f) * KK2 + j] = a0;
    g_e[(size_t)((b0 + bl + 1)*OO + f) * KK2 + j] = a1;
}

// ---------------------------------------------------------------------------
// K4: out = Te * e * Te^T with parity on h.
// one block per (b,f); 256 threads = (4 w's, 8 h-pairs); float4 stores.
// vs-phase uses all 256 threads (kh split across halves).
// ---------------------------------------------------------------------------
__global__ __launch_bounds__(256) void k4_synth(float* __restrict__ out) {
    __shared__ __align__(16) float vs[KK*132];     // [kh][w] padded
    __shared__ float es[KK2];
    __shared__ float xs[HH];
    int tid = threadIdx.x;
    int bf  = blockIdx.x;

    if (tid < HH) xs[tid] = g_xn[tid];
    if (tid >= 128 && tid < 128 + KK2) es[tid-128] = g_e[(size_t)bf * KK2 + (tid-128)];
    __syncthreads();

    // v[kh][w] via width recurrence; all 256 threads (kh split 0..3 / 4..8)
    {
        int w  = tid & 127;
        int hi = tid >> 7;              // 0: kh 0..3, 1: kh 4..8
        float xn = xs[w], x2 = xn + xn;
        float tw[KK];
        tw[0] = 1.0f; tw[1] = xn;
        #pragma unroll
        for (int k = 2; k < KK; k++) tw[k] = x2*tw[k-1] - tw[k-2];
        int kh0 = hi ? 4 : 0;
        int kh1 = hi ? 9 : 4;
        for (int kh = kh0; kh < kh1; kh++) {
            float sv = 0.0f;
            #pragma unroll
            for (int kw = 0; kw < KK; kw++) sv += es[kh*KK + kw] * tw[kw];
            vs[kh*132 + w] = sv;
        }
    }
    __syncthreads();

    int w4 = (tid & 31) * 4;
    int s  = tid >> 5;                  // 0..7 -> h pairs [s*8, s*8+8)
    float4 vr[KK];
    #pragma unroll
    for (int k = 0; k < KK; k++) vr[k] = *(const float4*)(vs + k*132 + w4);

    float* op = out + (size_t)bf * IMG + w4;
    #pragma unroll 4
    for (int pp = 0; pp < 8; pp++) {
        int h = s*8 + pp;               // lo row; hi = 127-h
        float xn = xs[h], x2 = xn + xn;
        float4 E, O;
        E.x = vr[0].x; E.y = vr[0].y; E.z = vr[0].z; E.w = vr[0].w;
        float t0 = 1.0f, t1 = xn;
        O.x = t1*vr[1].x; O.y = t1*vr[1].y; O.z = t1*vr[1].z; O.w = t1*vr[1].w;
        #pragma unroll
        for (int k = 2; k < KK; k++) {
            float t2 = x2*t1 - t0;
            if ((k & 1) == 0) {
                E.x += t2*vr[k].x; E.y += t2*vr[k].y;
                E.z += t2*vr[k].z; E.w += t2*vr[k].w;
            } else {
                O.x += t2*vr[k].x; O.y += t2*vr[k].y;
                O.z += t2*vr[k].z; O.w += t2*vr[k].w;
            }
            t0 = t1; t1 = t2;
        }
        float4 lo, hi;
        lo.x = E.x + O.x; lo.y = E.y + O.y; lo.z = E.z + O.z; lo.w = E.w + O.w;
        hi.x = E.x - O.x; hi.y = E.y - O.y; hi.z = E.z - O.z; hi.w = E.w - O.w;
        *(float4*)(op + h*WW)       = lo;
        *(float4*)(op + (127-h)*WW) = hi;
    }
}

// ---------------------------------------------------------------------------
extern "C" void kernel_launch(void* const* d_in, const int* in_sizes, int n_in,
                              void* d_out, int out_size) {
    const float* x  = (const float*)d_in[0];
    const float* Ww = (const float*)d_in[1];
    const float* Wh = (const float*)d_in[2];
    float* out = (float*)d_out;

    kA_setup_wc<<<1 + KK2, 256>>>(Ww, Wh);
    k1_analysis<<<BC, 128>>>(x);
    k_mix<<<KK2*4, 256>>>();
    k4_synth<<<BF, 256>>>(out);
}